// round 15
// baseline (speedup 1.0000x reference)
#include <cuda_runtime.h>

#define BB   2
#define NN   512
#define DD   256
#define HH   4
#define HDD  64
#define HDH  256

typedef unsigned long long ull;
#define ABS2 0x7fffffff7fffffffULL

__device__ __align__(16) float g_hq[BB*NN*HDH];
__device__ __align__(16) float g_hk[BB*NN*HDH];
__device__ __align__(16) float g_hv[BB*NN*HDH];
__device__ __align__(16) float g_sq[BB*NN*HH];

__device__ __forceinline__ ull add2(ull a, ull b) {
    ull r; asm("add.rn.f32x2 %0, %1, %2;" : "=l"(r) : "l"(a), "l"(b)); return r;
}
__device__ __forceinline__ ull fma2(ull a, ull b, ull c) {
    ull r; asm("fma.rn.f32x2 %0, %1, %2, %3;" : "=l"(r) : "l"(a), "l"(b), "l"(c)); return r;
}
__device__ __forceinline__ ull pack2(float lo, float hi) {
    ull r; asm("mov.b64 %0, {%1, %2};" : "=l"(r) : "f"(lo), "f"(hi)); return r;
}
__device__ __forceinline__ float2 unpack2(ull v) {
    float2 f; asm("mov.b64 {%0, %1}, %2;" : "=f"(f.x), "=f"(f.y) : "l"(v)); return f;
}
__device__ __forceinline__ void cp16(unsigned s, const void* g) {
    asm volatile("cp.async.ca.shared.global [%0], [%1], 16;" :: "r"(s), "l"(g));
}
#define CP_COMMIT() asm volatile("cp.async.commit_group;")
#define CP_WAIT1()  asm volatile("cp.async.wait_group 1;")
#define CP_WAIT0()  asm volatile("cp.async.wait_group 0;")

// ---------------------------------------------------------------------------
// Kernel 1: projections — r10-exact GEMM + fused-sq epilogue (unchanged,
// measured ~16.6us incl. sq). 16x128 tiles, 128 thr, 4x4 tile, 384 blocks.
// ---------------------------------------------------------------------------
__global__ __launch_bounds__(128) void proj_kernel(
    const float* __restrict__ q, const float* __restrict__ k, const float* __restrict__ v,
    const float* __restrict__ wq, const float* __restrict__ bq,
    const float* __restrict__ wv, const float* __restrict__ bv,
    const float* __restrict__ a_in)
{
    __shared__ float sx[2][16][20];
    __shared__ float sw[2][16][128];

    int bid = blockIdx.x;
    int m   = bid >> 7;
    int rem = bid & 127;
    int rt  = rem >> 1;
    int ct  = rem & 1;
    int r0 = rt * 16, c0 = ct * 128;

    const float* src  = (m==0) ? q : (m==1) ? k : v;
    const float* W    = (m<2)  ? wq : wv;
    const float* bias = (m<2)  ? bq : bv;
    float* dst        = (m==0) ? g_hq : (m==1) ? g_hk : g_hv;

    int tid = threadIdx.x;
    int ry  = tid >> 5;
    int cx  = tid & 31;

    float4 b4 = *(const float4*)&bias[c0 + cx*4];
    float4 acc0 = b4, acc1 = b4, acc2 = b4, acc3 = b4;

    int xrow = tid >> 2, xdg = tid & 3;

    float4 xr = make_float4(0.f,0.f,0.f,0.f);
    if (tid < 64) xr = *(const float4*)&src[(size_t)(r0 + xrow)*DD + xdg*4];
    float4 wr[4];
    #pragma unroll
    for (int j = 0; j < 4; j++) {
        int idx = tid + j*128;
        wr[j] = *(const float4*)&W[(size_t)(idx>>5)*DD + c0 + (idx&31)*4];
    }

    if (tid < 64) {
        sx[0][xdg*4+0][xrow] = xr.x;
        sx[0][xdg*4+1][xrow] = xr.y;
        sx[0][xdg*4+2][xrow] = xr.z;
        sx[0][xdg*4+3][xrow] = xr.w;
    }
    #pragma unroll
    for (int j = 0; j < 4; j++) {
        int idx = tid + j*128;
        *(float4*)&sw[0][idx>>5][(idx&31)*4] = wr[j];
    }
    __syncthreads();

    #pragma unroll 1
    for (int c = 0; c < 16; c++) {
        int buf = c & 1;
        if (c < 15) {
            int dbase = (c + 1) * 16;
            if (tid < 64) xr = *(const float4*)&src[(size_t)(r0 + xrow)*DD + dbase + xdg*4];
            #pragma unroll
            for (int j = 0; j < 4; j++) {
                int idx = tid + j*128;
                wr[j] = *(const float4*)&W[(size_t)(dbase + (idx>>5))*DD + c0 + (idx&31)*4];
            }
        }

        #pragma unroll
        for (int kk = 0; kk < 16; kk++) {
            float4 xv = *(const float4*)&sx[buf][kk][ry*4];
            float4 wv = *(const float4*)&sw[buf][kk][cx*4];
            acc0.x = fmaf(xv.x, wv.x, acc0.x);
            acc0.y = fmaf(xv.x, wv.y, acc0.y);
            acc0.z = fmaf(xv.x, wv.z, acc0.z);
            acc0.w = fmaf(xv.x, wv.w, acc0.w);
            acc1.x = fmaf(xv.y, wv.x, acc1.x);
            acc1.y = fmaf(xv.y, wv.y, acc1.y);
            acc1.z = fmaf(xv.y, wv.z, acc1.z);
            acc1.w = fmaf(xv.y, wv.w, acc1.w);
            acc2.x = fmaf(xv.z, wv.x, acc2.x);
            acc2.y = fmaf(xv.z, wv.y, acc2.y);
            acc2.z = fmaf(xv.z, wv.z, acc2.z);
            acc2.w = fmaf(xv.z, wv.w, acc2.w);
            acc3.x = fmaf(xv.w, wv.x, acc3.x);
            acc3.y = fmaf(xv.w, wv.y, acc3.y);
            acc3.z = fmaf(xv.w, wv.z, acc3.z);
            acc3.w = fmaf(xv.w, wv.w, acc3.w);
        }

        if (c < 15) {
            int nbuf = buf ^ 1;
            if (tid < 64) {
                sx[nbuf][xdg*4+0][xrow] = xr.x;
                sx[nbuf][xdg*4+1][xrow] = xr.y;
                sx[nbuf][xdg*4+2][xrow] = xr.z;
                sx[nbuf][xdg*4+3][xrow] = xr.w;
            }
            #pragma unroll
            for (int j = 0; j < 4; j++) {
                int idx = tid + j*128;
                *(float4*)&sw[nbuf][idx>>5][(idx&31)*4] = wr[j];
            }
        }
        __syncthreads();
    }

    float4* dst4 = (float4*)dst;
    size_t obase = (size_t)(r0 + ry*4) * 64 + (c0 >> 2) + cx;
    dst4[obase + 0*64] = acc0;
    dst4[obase + 1*64] = acc1;
    dst4[obase + 2*64] = acc2;
    dst4[obase + 3*64] = acc3;

    if (m == 0) {
        int lane = cx;
        int h = ct*2 + (lane >> 4);
        float4 av = *(const float4*)&a_in[(lane*4) & 63];
        float p0 = acc0.x*av.x + acc0.y*av.y + acc0.z*av.z + acc0.w*av.w;
        float p1 = acc1.x*av.x + acc1.y*av.y + acc1.z*av.z + acc1.w*av.w;
        float p2 = acc2.x*av.x + acc2.y*av.y + acc2.z*av.z + acc2.w*av.w;
        float p3 = acc3.x*av.x + acc3.y*av.y + acc3.z*av.z + acc3.w*av.w;
        #pragma unroll
        for (int o = 8; o; o >>= 1) {
            p0 += __shfl_xor_sync(0xffffffffu, p0, o);
            p1 += __shfl_xor_sync(0xffffffffu, p1, o);
            p2 += __shfl_xor_sync(0xffffffffu, p2, o);
            p3 += __shfl_xor_sync(0xffffffffu, p3, o);
        }
        if ((lane & 15) == 0) {
            int rb = r0 + ry*4;
            g_sq[(rb+0)*HH + h] = 0.6f * p0;
            g_sq[(rb+1)*HH + h] = 0.6f * p1;
            g_sq[(rb+2)*HH + h] = 0.6f * p2;
            g_sq[(rb+3)*HH + h] = 0.6f * p3;
        }
    }
}

// ---------------------------------------------------------------------------
// Kernel 2: main GAT — occupancy doubled: i-tile 8 -> 512 blocks x 8 warps
// = 4096 warps (27.7/SM), 3 blocks/SM (smem 55.8KB, regs capped 85 via
// 4 f-passes). cp.async double-buffered 64-row chunks for hq and hv.
// Lane layout phase A: ii = lane&7, jq = lane>>3.
// ---------------------------------------------------------------------------
__global__ __launch_bounds__(256, 3) void gat_main(float* __restrict__ out_h,
                                                   float* __restrict__ out_e,
                                                   const float* __restrict__ a_in)
{
    extern __shared__ float sm[];
    float* sh_e  = sm;                    // 8*516  = 4128 fl
    float* sh_x  = sh_e + 8*516;          // 2*64*64 = 8192 fl (double buffer)
    float* sh_hk = sh_x + 2*64*64;        // 8*68   = 544 fl
    float* sh_sq = sh_hk + 8*68;          // 512 fl
    float* sh_p  = sh_sq + 512;           // 8*64   = 512 fl
    float* sh_aa = sh_p + 8*64;           // 64 fl
    // total 13952 floats = 55808 B

    int bid = blockIdx.x;                 // 512 = b(2) * h(4) * it(64)
    int b   = bid >> 8;
    int h   = (bid >> 6) & 3;
    int i0  = (bid & 63) * 8;
    int tid = threadIdx.x;
    int lane = tid & 31;
    int wid  = tid >> 5;

    unsigned xsb = (unsigned)__cvta_generic_to_shared(sh_x);
    int sr = tid >> 4, sf = tid & 15;     // staging: 16 rows x 16 fg per pass

    // prologue: async-fetch hq chunk 0 (64 rows) into buffer 0
    {
        const float* gsrc = g_hq + (size_t)(b*NN)*HDH + h*HDD;
        #pragma unroll
        for (int rr = 0; rr < 4; rr++) {
            int r = rr*16 + sr;
            cp16(xsb + (unsigned)((r*16 + sf)*16), gsrc + (size_t)r*HDH + sf*4);
        }
        CP_COMMIT();
    }

    // stage hk [8 x 64] (stride 68), sq[512], aa[64]
    if (tid < 128) {
        int r = tid >> 4, fgi = tid & 15;
        float4 kv = ((const float4*)(g_hk + (size_t)(b*NN + i0 + r)*HDH + h*HDD))[fgi];
        *(float4*)&sh_hk[r*68 + fgi*4] = kv;
    }
    for (int t = tid; t < NN; t += 256)
        sh_sq[t] = g_sq[(b*NN + t)*HH + h];
    if (tid < HDD) sh_aa[tid] = 0.4f * a_in[tid];

    int ii = lane & 7;
    int jq = lane >> 3;       // 0..3

    // ---- phase A: logits over 8 hq chunks of 64 rows, pipelined ----
    #pragma unroll 1
    for (int c = 0; c < 8; c++) {
        if (c < 7) {
            const float* gsrc = g_hq + (size_t)(b*NN + (c+1)*64)*HDH + h*HDD;
            unsigned boff = (unsigned)(((c+1)&1) * 16384);
            #pragma unroll
            for (int rr = 0; rr < 4; rr++) {
                int r = rr*16 + sr;
                cp16(xsb + boff + (unsigned)((r*16 + sf)*16), gsrc + (size_t)r*HDH + sf*4);
            }
            CP_COMMIT();
            CP_WAIT1();
        } else {
            CP_WAIT0();
        }
        __syncthreads();

        const float* xb = sh_x + (c&1)*4096;
        int cs = c*64;

        float accj[2];
        #pragma unroll 1
        for (int pass = 0; pass < 4; pass++) {
            ull kr[8], aw[8];
            {
                const ulonglong2* kp = (const ulonglong2*)(sh_hk + ii*68 + pass*16);
                const ulonglong2* ap = (const ulonglong2*)(sh_aa + pass*16);
                #pragma unroll
                for (int g = 0; g < 4; g++) {
                    ulonglong2 kk = kp[g];
                    kr[2*g] = kk.x; kr[2*g+1] = kk.y;
                    ulonglong2 av = ap[g];
                    aw[2*g] = av.x; aw[2*g+1] = av.y;
                }
            }
            #pragma unroll
            for (int t = 0; t < 2; t++) {
                int jj = wid*8 + t*4 + jq;
                const ulonglong2* q2 = (const ulonglong2*)(xb + jj*64 + pass*16);
                ull acc0 = 0ULL, acc1 = 0ULL;
                #pragma unroll
                for (int g = 0; g < 4; g++) {
                    ulonglong2 qq = q2[g];
                    ull t0 = add2(qq.x, kr[2*g]) & ABS2;
                    acc0 = fma2(aw[2*g], t0, acc0);
                    ull t1 = add2(qq.y, kr[2*g+1]) & ABS2;
                    acc1 = fma2(aw[2*g+1], t1, acc1);
                }
                float2 a0 = unpack2(acc0), a1 = unpack2(acc1);
                float s = (a0.x + a0.y) + (a1.x + a1.y);
                if (pass == 0) accj[t] = s;
                else           accj[t] += s;
            }
        }
        #pragma unroll
        for (int t = 0; t < 2; t++) {
            int j = cs + wid*8 + t*4 + jq;
            sh_e[ii*516 + j] = accj[t] + sh_sq[j];
        }
        __syncthreads();
    }

    // ---- phase B: row softmax (warp w -> row w; 8 rows, 8 warps) ----
    {
        float* row = sh_e + wid*516;
        float mx = -1e30f;
        for (int j = lane; j < NN; j += 32) mx = fmaxf(mx, row[j]);
        #pragma unroll
        for (int o = 16; o; o >>= 1) mx = fmaxf(mx, __shfl_xor_sync(0xffffffffu, mx, o));
        float s = 0.f;
        for (int j = lane; j < NN; j += 32) {
            float ex = __expf(row[j] - mx);
            row[j] = ex;
            s += ex;
        }
        #pragma unroll
        for (int o = 16; o; o >>= 1) s += __shfl_xor_sync(0xffffffffu, s, o);
        float inv = 1.f / s;
        for (int j = lane; j < NN; j += 32) row[j] *= inv;
    }
    __syncthreads();

    // ---- C: issue first hv fetch, then e-writes overlap it ----
    {
        const float* gsrc = g_hv + (size_t)(b*NN)*HDH + h*HDD;
        #pragma unroll
        for (int rr = 0; rr < 4; rr++) {
            int r = rr*16 + sr;
            cp16(xsb + (unsigned)((r*16 + sf)*16), gsrc + (size_t)r*HDH + sf*4);
        }
        CP_COMMIT();
    }

    // phase C1: write e [B,N,N,H]
    {
        float* ebase = out_e + ((size_t)(b*NN + i0) * NN) * HH + h;
        for (int t = tid; t < 8*512; t += 256) {
            int i = t >> 9, j = t & 511;
            ebase[(size_t)(i*NN + j) * HH] = sh_e[i*516 + j];
        }
    }

    // phase C2: AV over 8 hv chunks (pipelined); warp -> 2 rows, j-half split
    {
        int wq = wid & 3;
        int jhalf = wid >> 2;
        int r = 2*wq + (lane >> 4);      // this lane's output row (0..7)
        int fg = lane & 15;

        ull a00 = 0ULL, a01 = 0ULL;

        #pragma unroll 1
        for (int c = 0; c < 8; c++) {
            if (c < 7) {
                const float* gsrc = g_hv + (size_t)(b*NN + (c+1)*64)*HDH + h*HDD;
                unsigned boff = (unsigned)(((c+1)&1) * 16384);
                #pragma unroll
                for (int rr = 0; rr < 4; rr++) {
                    int rw = rr*16 + sr;
                    cp16(xsb + boff + (unsigned)((rw*16 + sf)*16), gsrc + (size_t)rw*HDH + sf*4);
                }
                CP_COMMIT();
                CP_WAIT1();
            } else {
                CP_WAIT0();
            }
            __syncthreads();

            const float* xb = sh_x + (c&1)*4096;
            int cs = c*64;
            int jb = jhalf * 32;

            #pragma unroll 2
            for (int qv = 0; qv < 32; qv += 4) {
                int jj = jb + qv;
                float4 e0 = *(const float4*)&sh_e[r*516 + cs + jj];
                {
                    ulonglong2 vv = *(const ulonglong2*)(xb + (jj+0)*64 + fg*4);
                    ull ev = pack2(e0.x, e0.x);
                    a00 = fma2(ev, vv.x, a00); a01 = fma2(ev, vv.y, a01);
                }
                {
                    ulonglong2 vv = *(const ulonglong2*)(xb + (jj+1)*64 + fg*4);
                    ull ev = pack2(e0.y, e0.y);
                    a00 = fma2(ev, vv.x, a00); a01 = fma2(ev, vv.y, a01);
                }
                {
                    ulonglong2 vv = *(const ulonglong2*)(xb + (jj+2)*64 + fg*4);
                    ull ev = pack2(e0.z, e0.z);
                    a00 = fma2(ev, vv.x, a00); a01 = fma2(ev, vv.y, a01);
                }
                {
                    ulonglong2 vv = *(const ulonglong2*)(xb + (jj+3)*64 + fg*4);
                    ull ev = pack2(e0.w, e0.w);
                    a00 = fma2(ev, vv.x, a00); a01 = fma2(ev, vv.y, a01);
                }
            }
            __syncthreads();
        }

        if (jhalf == 1) {
            *(ulonglong2*)&sh_p[r*64 + fg*4] = make_ulonglong2(a00, a01);
        }
        __syncthreads();
        if (jhalf == 0) {
            ulonglong2 p0 = *(const ulonglong2*)&sh_p[r*64 + fg*4];
            a00 = add2(a00, p0.x); a01 = add2(a01, p0.y);
            float2 f0 = unpack2(a00), f1 = unpack2(a01);
            float4 ra = make_float4(fmaxf(f0.x,0.f), fmaxf(f0.y,0.f),
                                    fmaxf(f1.x,0.f), fmaxf(f1.y,0.f));
            *(float4*)&out_h[(size_t)(b*NN + i0 + r)*HDH + h*HDD + fg*4] = ra;
        }
    }
}

// ---------------------------------------------------------------------------
extern "C" void kernel_launch(void* const* d_in, const int* in_sizes, int n_in,
                              void* d_out, int out_size)
{
    const float* q  = (const float*)d_in[0];
    const float* k  = (const float*)d_in[1];
    const float* v  = (const float*)d_in[2];
    const float* wq = (const float*)d_in[3];
    const float* bq = (const float*)d_in[4];
    const float* wv = (const float*)d_in[5];
    const float* bv = (const float*)d_in[6];
    const float* a  = (const float*)d_in[7];

    float* out_h = (float*)d_out;
    float* out_e = out_h + (size_t)BB*NN*HDH;

    const int smem_main = (8*516 + 2*64*64 + 8*68 + 512 + 8*64 + 64) * (int)sizeof(float); // 55808
    cudaFuncSetAttribute(gat_main, cudaFuncAttributeMaxDynamicSharedMemorySize, smem_main);

    proj_kernel<<<384, 128>>>(q, k, v, wq, bq, wv, bv, a);
    gat_main<<<512, 256, smem_main>>>(out_h, out_e, a);
}

// round 16
// speedup vs baseline: 1.4654x; 1.4654x over previous
#include <cuda_runtime.h>

#define BB   2
#define NN   512
#define DD   256
#define HH   4
#define HDD  64
#define HDH  256

typedef unsigned long long ull;
#define ABS2 0x7fffffff7fffffffULL

__device__ __align__(16) float g_hq[BB*NN*HDH];
__device__ __align__(16) float g_hk[BB*NN*HDH];
__device__ __align__(16) float g_hv[BB*NN*HDH];
__device__ __align__(16) float g_sq[BB*NN*HH];

__device__ __forceinline__ ull add2(ull a, ull b) {
    ull r; asm("add.rn.f32x2 %0, %1, %2;" : "=l"(r) : "l"(a), "l"(b)); return r;
}
__device__ __forceinline__ ull fma2(ull a, ull b, ull c) {
    ull r; asm("fma.rn.f32x2 %0, %1, %2, %3;" : "=l"(r) : "l"(a), "l"(b), "l"(c)); return r;
}
__device__ __forceinline__ ull pack2(float lo, float hi) {
    ull r; asm("mov.b64 %0, {%1, %2};" : "=l"(r) : "f"(lo), "f"(hi)); return r;
}
__device__ __forceinline__ float2 unpack2(ull v) {
    float2 f; asm("mov.b64 {%0, %1}, %2;" : "=f"(f.x), "=f"(f.y) : "l"(v)); return f;
}
__device__ __forceinline__ void cp16(unsigned s, const void* g) {
    asm volatile("cp.async.ca.shared.global [%0], [%1], 16;" :: "r"(s), "l"(g));
}
#define CP_COMMIT() asm volatile("cp.async.commit_group;")
#define CP_WAIT1()  asm volatile("cp.async.wait_group 1;")
#define CP_WAIT0()  asm volatile("cp.async.wait_group 0;")

// ---------------------------------------------------------------------------
// Kernel 1: projections — r10-exact GEMM + fused-sq epilogue (frozen).
// ---------------------------------------------------------------------------
__global__ __launch_bounds__(128) void proj_kernel(
    const float* __restrict__ q, const float* __restrict__ k, const float* __restrict__ v,
    const float* __restrict__ wq, const float* __restrict__ bq,
    const float* __restrict__ wv, const float* __restrict__ bv,
    const float* __restrict__ a_in)
{
    __shared__ float sx[2][16][20];
    __shared__ float sw[2][16][128];

    int bid = blockIdx.x;
    int m   = bid >> 7;
    int rem = bid & 127;
    int rt  = rem >> 1;
    int ct  = rem & 1;
    int r0 = rt * 16, c0 = ct * 128;

    const float* src  = (m==0) ? q : (m==1) ? k : v;
    const float* W    = (m<2)  ? wq : wv;
    const float* bias = (m<2)  ? bq : bv;
    float* dst        = (m==0) ? g_hq : (m==1) ? g_hk : g_hv;

    int tid = threadIdx.x;
    int ry  = tid >> 5;
    int cx  = tid & 31;

    float4 b4 = *(const float4*)&bias[c0 + cx*4];
    float4 acc0 = b4, acc1 = b4, acc2 = b4, acc3 = b4;

    int xrow = tid >> 2, xdg = tid & 3;

    float4 xr = make_float4(0.f,0.f,0.f,0.f);
    if (tid < 64) xr = *(const float4*)&src[(size_t)(r0 + xrow)*DD + xdg*4];
    float4 wr[4];
    #pragma unroll
    for (int j = 0; j < 4; j++) {
        int idx = tid + j*128;
        wr[j] = *(const float4*)&W[(size_t)(idx>>5)*DD + c0 + (idx&31)*4];
    }

    if (tid < 64) {
        sx[0][xdg*4+0][xrow] = xr.x;
        sx[0][xdg*4+1][xrow] = xr.y;
        sx[0][xdg*4+2][xrow] = xr.z;
        sx[0][xdg*4+3][xrow] = xr.w;
    }
    #pragma unroll
    for (int j = 0; j < 4; j++) {
        int idx = tid + j*128;
        *(float4*)&sw[0][idx>>5][(idx&31)*4] = wr[j];
    }
    __syncthreads();

    #pragma unroll 1
    for (int c = 0; c < 16; c++) {
        int buf = c & 1;
        if (c < 15) {
            int dbase = (c + 1) * 16;
            if (tid < 64) xr = *(const float4*)&src[(size_t)(r0 + xrow)*DD + dbase + xdg*4];
            #pragma unroll
            for (int j = 0; j < 4; j++) {
                int idx = tid + j*128;
                wr[j] = *(const float4*)&W[(size_t)(dbase + (idx>>5))*DD + c0 + (idx&31)*4];
            }
        }

        #pragma unroll
        for (int kk = 0; kk < 16; kk++) {
            float4 xv = *(const float4*)&sx[buf][kk][ry*4];
            float4 wv = *(const float4*)&sw[buf][kk][cx*4];
            acc0.x = fmaf(xv.x, wv.x, acc0.x);
            acc0.y = fmaf(xv.x, wv.y, acc0.y);
            acc0.z = fmaf(xv.x, wv.z, acc0.z);
            acc0.w = fmaf(xv.x, wv.w, acc0.w);
            acc1.x = fmaf(xv.y, wv.x, acc1.x);
            acc1.y = fmaf(xv.y, wv.y, acc1.y);
            acc1.z = fmaf(xv.y, wv.z, acc1.z);
            acc1.w = fmaf(xv.y, wv.w, acc1.w);
            acc2.x = fmaf(xv.z, wv.x, acc2.x);
            acc2.y = fmaf(xv.z, wv.y, acc2.y);
            acc2.z = fmaf(xv.z, wv.z, acc2.z);
            acc2.w = fmaf(xv.z, wv.w, acc2.w);
            acc3.x = fmaf(xv.w, wv.x, acc3.x);
            acc3.y = fmaf(xv.w, wv.y, acc3.y);
            acc3.z = fmaf(xv.w, wv.z, acc3.z);
            acc3.w = fmaf(xv.w, wv.w, acc3.w);
        }

        if (c < 15) {
            int nbuf = buf ^ 1;
            if (tid < 64) {
                sx[nbuf][xdg*4+0][xrow] = xr.x;
                sx[nbuf][xdg*4+1][xrow] = xr.y;
                sx[nbuf][xdg*4+2][xrow] = xr.z;
                sx[nbuf][xdg*4+3][xrow] = xr.w;
            }
            #pragma unroll
            for (int j = 0; j < 4; j++) {
                int idx = tid + j*128;
                *(float4*)&sw[nbuf][idx>>5][(idx&31)*4] = wr[j];
            }
        }
        __syncthreads();
    }

    float4* dst4 = (float4*)dst;
    size_t obase = (size_t)(r0 + ry*4) * 64 + (c0 >> 2) + cx;
    dst4[obase + 0*64] = acc0;
    dst4[obase + 1*64] = acc1;
    dst4[obase + 2*64] = acc2;
    dst4[obase + 3*64] = acc3;

    if (m == 0) {
        int lane = cx;
        int h = ct*2 + (lane >> 4);
        float4 av = *(const float4*)&a_in[(lane*4) & 63];
        float p0 = acc0.x*av.x + acc0.y*av.y + acc0.z*av.z + acc0.w*av.w;
        float p1 = acc1.x*av.x + acc1.y*av.y + acc1.z*av.z + acc1.w*av.w;
        float p2 = acc2.x*av.x + acc2.y*av.y + acc2.z*av.z + acc2.w*av.w;
        float p3 = acc3.x*av.x + acc3.y*av.y + acc3.z*av.z + acc3.w*av.w;
        #pragma unroll
        for (int o = 8; o; o >>= 1) {
            p0 += __shfl_xor_sync(0xffffffffu, p0, o);
            p1 += __shfl_xor_sync(0xffffffffu, p1, o);
            p2 += __shfl_xor_sync(0xffffffffu, p2, o);
            p3 += __shfl_xor_sync(0xffffffffu, p3, o);
        }
        if ((lane & 15) == 0) {
            int rb = r0 + ry*4;
            g_sq[(rb+0)*HH + h] = 0.6f * p0;
            g_sq[(rb+1)*HH + h] = 0.6f * p1;
            g_sq[(rb+2)*HH + h] = 0.6f * p2;
            g_sq[(rb+3)*HH + h] = 0.6f * p3;
        }
    }
}

// ---------------------------------------------------------------------------
// Kernel 2: main GAT — r14 skeleton (16-row i-tile, 256 blocks, 256 thr,
// 2/SM, 2-pass). Changes: C1 fused into softmax; C2 4 rows/lane (vv LDS
// halved, 2-region sh_p tree reduce); hv chunks 0+1 prefetched before softmax.
// ---------------------------------------------------------------------------
__global__ __launch_bounds__(256, 2) void gat_main(float* __restrict__ out_h,
                                                   float* __restrict__ out_e,
                                                   const float* __restrict__ a_in)
{
    extern __shared__ float sm[];
    float* sh_e  = sm;                    // 16*516  = 8256
    float* sh_x  = sh_e + 16*516;         // 2*128*64 = 16384 (double buffer)
    float* sh_hk = sh_x + 2*128*64;       // 16*68   = 1088
    float* sh_sq = sh_hk + 16*68;         // 512
    float* sh_p  = sh_sq + 512;           // 2*16*64 = 2048
    float* sh_aa = sh_p + 2*16*64;        // 64
    // total 28352 floats = 113408 B

    int bid = blockIdx.x;
    int b   = bid >> 7;
    int h   = (bid >> 5) & 3;
    int i0  = (bid & 31) * 16;
    int tid = threadIdx.x;
    int lane = tid & 31;
    int wid  = tid >> 5;

    unsigned xsb = (unsigned)__cvta_generic_to_shared(sh_x);
    int sr = tid >> 4, sf = tid & 15;

    // prologue: async-fetch hq chunk 0 into buffer 0
    {
        const float* gsrc = g_hq + (size_t)(b*NN)*HDH + h*HDD;
        #pragma unroll
        for (int rr = 0; rr < 8; rr++) {
            int r = rr*16 + sr;
            cp16(xsb + (unsigned)((r*16 + sf)*16), gsrc + (size_t)r*HDH + sf*4);
        }
        CP_COMMIT();
    }

    // stage hk [16 x 64] (stride 68), sq[512], aa[64]
    {
        int r = tid >> 4, fgi = tid & 15;
        float4 kv = ((const float4*)(g_hk + (size_t)(b*NN + i0 + r)*HDH + h*HDD))[fgi];
        *(float4*)&sh_hk[r*68 + fgi*4] = kv;
    }
    for (int t = tid; t < NN; t += 256)
        sh_sq[t] = g_sq[(b*NN + t)*HH + h];
    if (tid < HDD) sh_aa[tid] = 0.4f * a_in[tid];

    int ii = lane & 15;
    int jh = lane >> 4;

    // ---- phase A: logits over 4 hq chunks of 128 rows, pipelined ----
    #pragma unroll 1
    for (int c = 0; c < 4; c++) {
        if (c < 3) {
            const float* gsrc = g_hq + (size_t)(b*NN + (c+1)*128)*HDH + h*HDD;
            unsigned boff = (unsigned)(((c+1)&1) * 32768);
            #pragma unroll
            for (int rr = 0; rr < 8; rr++) {
                int r = rr*16 + sr;
                cp16(xsb + boff + (unsigned)((r*16 + sf)*16), gsrc + (size_t)r*HDH + sf*4);
            }
            CP_COMMIT();
            CP_WAIT1();
        } else {
            CP_WAIT0();
        }
        __syncthreads();

        const float* xb = sh_x + (c&1)*8192;
        int cs = c*128;

        float accj[8];
        #pragma unroll 1
        for (int pass = 0; pass < 2; pass++) {
            ull kr[16], aw[16];
            {
                const ulonglong2* kp = (const ulonglong2*)(sh_hk + ii*68 + pass*32);
                const ulonglong2* ap = (const ulonglong2*)(sh_aa + pass*32);
                #pragma unroll
                for (int g = 0; g < 8; g++) {
                    ulonglong2 kk = kp[g];
                    kr[2*g] = kk.x; kr[2*g+1] = kk.y;
                    ulonglong2 av = ap[g];
                    aw[2*g] = av.x; aw[2*g+1] = av.y;
                }
            }
            #pragma unroll 2
            for (int t = 0; t < 8; t++) {
                int jj = wid*16 + t*2 + jh;
                const ulonglong2* q2 = (const ulonglong2*)(xb + jj*64 + pass*32);
                ull acc0 = 0ULL, acc1 = 0ULL;
                #pragma unroll
                for (int g = 0; g < 8; g++) {
                    ulonglong2 qq = q2[g];
                    ull t0 = add2(qq.x, kr[2*g]) & ABS2;
                    acc0 = fma2(aw[2*g], t0, acc0);
                    ull t1 = add2(qq.y, kr[2*g+1]) & ABS2;
                    acc1 = fma2(aw[2*g+1], t1, acc1);
                }
                float2 a0 = unpack2(acc0), a1 = unpack2(acc1);
                float s = (a0.x + a0.y) + (a1.x + a1.y);
                if (pass == 0) accj[t] = s;
                else           accj[t] += s;
            }
        }
        #pragma unroll
        for (int t = 0; t < 8; t++) {
            int j = cs + wid*16 + t*2 + jh;
            sh_e[ii*516 + j] = accj[t] + sh_sq[j];
        }
        __syncthreads();
    }

    // ---- prefetch hv chunks 0 AND 1 now (fly through softmax + e-writes) ----
    {
        const float* gsrc = g_hv + (size_t)(b*NN)*HDH + h*HDD;
        #pragma unroll
        for (int rr = 0; rr < 8; rr++) {
            int r = rr*16 + sr;
            cp16(xsb + (unsigned)((r*16 + sf)*16), gsrc + (size_t)r*HDH + sf*4);
        }
        CP_COMMIT();
        gsrc += (size_t)128*HDH;
        #pragma unroll
        for (int rr = 0; rr < 8; rr++) {
            int r = rr*16 + sr;
            cp16(xsb + 32768u + (unsigned)((r*16 + sf)*16), gsrc + (size_t)r*HDH + sf*4);
        }
        CP_COMMIT();
    }

    // ---- phase B: row softmax, FUSED with out_e write (warp w -> rows 2w,2w+1) ----
    #pragma unroll
    for (int rr = 0; rr < 2; rr++) {
        int row_i = 2*wid + rr;
        float* row = sh_e + row_i*516;
        float mx = -1e30f;
        for (int j = lane; j < NN; j += 32) mx = fmaxf(mx, row[j]);
        #pragma unroll
        for (int o = 16; o; o >>= 1) mx = fmaxf(mx, __shfl_xor_sync(0xffffffffu, mx, o));
        float s = 0.f;
        for (int j = lane; j < NN; j += 32) {
            float ex = __expf(row[j] - mx);
            row[j] = ex;
            s += ex;
        }
        #pragma unroll
        for (int o = 16; o; o >>= 1) s += __shfl_xor_sync(0xffffffffu, s, o);
        float inv = 1.f / s;
        float* eg = out_e + ((size_t)(b*NN + i0 + row_i) * NN) * HH + h;
        for (int j = lane; j < NN; j += 32) {
            float val = row[j] * inv;
            row[j] = val;
            eg[(size_t)j * HH] = val;
        }
    }
    __syncthreads();

    // ---- phase C2: AV, 4 rows per lane, j-quarter split, pipelined hv ----
    {
        int fg   = lane & 15;
        int rh   = lane >> 4;        // 0/1
        int wjq  = wid >> 1;         // j-quarter 0..3
        int wrh  = wid & 1;          // row octet
        int rbase = wrh*8 + rh*4;    // lane's rows: rbase..rbase+3

        ull acc[4][2];
        #pragma unroll
        for (int k2 = 0; k2 < 4; k2++) { acc[k2][0] = 0ULL; acc[k2][1] = 0ULL; }

        #pragma unroll 1
        for (int c = 0; c < 4; c++) {
            if (c < 3) { CP_WAIT1(); } else { CP_WAIT0(); }
            __syncthreads();

            const float* xb = sh_x + (c&1)*8192;
            int cs = c*128;
            int jb = wjq * 32;

            #pragma unroll 2
            for (int qv = 0; qv < 32; qv += 4) {
                int jj = jb + qv;
                float4 e0 = *(const float4*)&sh_e[(rbase+0)*516 + cs + jj];
                float4 e1 = *(const float4*)&sh_e[(rbase+1)*516 + cs + jj];
                float4 e2 = *(const float4*)&sh_e[(rbase+2)*516 + cs + jj];
                float4 e3 = *(const float4*)&sh_e[(rbase+3)*516 + cs + jj];
                #pragma unroll
                for (int p = 0; p < 4; p++) {
                    ulonglong2 vv = *(const ulonglong2*)(xb + (jj+p)*64 + fg*4);
                    float c0 = (p==0)?e0.x:(p==1)?e0.y:(p==2)?e0.z:e0.w;
                    float c1 = (p==0)?e1.x:(p==1)?e1.y:(p==2)?e1.z:e1.w;
                    float c2 = (p==0)?e2.x:(p==1)?e2.y:(p==2)?e2.z:e2.w;
                    float c3 = (p==0)?e3.x:(p==1)?e3.y:(p==2)?e3.z:e3.w;
                    ull ev0 = pack2(c0, c0);
                    ull ev1 = pack2(c1, c1);
                    ull ev2 = pack2(c2, c2);
                    ull ev3 = pack2(c3, c3);
                    acc[0][0] = fma2(ev0, vv.x, acc[0][0]); acc[0][1] = fma2(ev0, vv.y, acc[0][1]);
                    acc[1][0] = fma2(ev1, vv.x, acc[1][0]); acc[1][1] = fma2(ev1, vv.y, acc[1][1]);
                    acc[2][0] = fma2(ev2, vv.x, acc[2][0]); acc[2][1] = fma2(ev2, vv.y, acc[2][1]);
                    acc[3][0] = fma2(ev3, vv.x, acc[3][0]); acc[3][1] = fma2(ev3, vv.y, acc[3][1]);
                }
            }
            __syncthreads();

            if (c < 2) {
                const float* gsrc = g_hv + (size_t)(b*NN + (c+2)*128)*HDH + h*HDD;
                unsigned boff = (unsigned)((c&1) * 32768);
                #pragma unroll
                for (int rr = 0; rr < 8; rr++) {
                    int r = rr*16 + sr;
                    cp16(xsb + boff + (unsigned)((r*16 + sf)*16), gsrc + (size_t)r*HDH + sf*4);
                }
                CP_COMMIT();
            }
        }

        // tree reduce across j-quarters: (1->0), (3->2), then (2->0)
        if (wjq == 1 || wjq == 3) {
            float* pr = sh_p + (wjq >> 1) * 1024;
            #pragma unroll
            for (int k2 = 0; k2 < 4; k2++)
                *(ulonglong2*)&pr[(rbase+k2)*64 + fg*4] = make_ulonglong2(acc[k2][0], acc[k2][1]);
        }
        __syncthreads();
        if (wjq == 0 || wjq == 2) {
            const float* pr = sh_p + (wjq >> 1) * 1024;
            #pragma unroll
            for (int k2 = 0; k2 < 4; k2++) {
                ulonglong2 pv = *(const ulonglong2*)&pr[(rbase+k2)*64 + fg*4];
                acc[k2][0] = add2(acc[k2][0], pv.x);
                acc[k2][1] = add2(acc[k2][1], pv.y);
            }
        }
        __syncthreads();
        if (wjq == 2) {
            float* pr = sh_p;
            #pragma unroll
            for (int k2 = 0; k2 < 4; k2++)
                *(ulonglong2*)&pr[(rbase+k2)*64 + fg*4] = make_ulonglong2(acc[k2][0], acc[k2][1]);
        }
        __syncthreads();
        if (wjq == 0) {
            #pragma unroll
            for (int k2 = 0; k2 < 4; k2++) {
                ulonglong2 pv = *(const ulonglong2*)&sh_p[(rbase+k2)*64 + fg*4];
                acc[k2][0] = add2(acc[k2][0], pv.x);
                acc[k2][1] = add2(acc[k2][1], pv.y);
                float2 f0 = unpack2(acc[k2][0]), f1 = unpack2(acc[k2][1]);
                float4 ra = make_float4(fmaxf(f0.x,0.f), fmaxf(f0.y,0.f),
                                        fmaxf(f1.x,0.f), fmaxf(f1.y,0.f));
                *(float4*)&out_h[(size_t)(b*NN + i0 + rbase + k2)*HDH + h*HDD + fg*4] = ra;
            }
        }
    }
}

// ---------------------------------------------------------------------------
extern "C" void kernel_launch(void* const* d_in, const int* in_sizes, int n_in,
                              void* d_out, int out_size)
{
    const float* q  = (const float*)d_in[0];
    const float* k  = (const float*)d_in[1];
    const float* v  = (const float*)d_in[2];
    const float* wq = (const float*)d_in[3];
    const float* bq = (const float*)d_in[4];
    const float* wv = (const float*)d_in[5];
    const float* bv = (const float*)d_in[6];
    const float* a  = (const float*)d_in[7];

    float* out_h = (float*)d_out;
    float* out_e = out_h + (size_t)BB*NN*HDH;

    const int smem_main = (16*516 + 2*128*64 + 16*68 + 512 + 2*16*64 + 64) * (int)sizeof(float); // 113408
    cudaFuncSetAttribute(gat_main, cudaFuncAttributeMaxDynamicSharedMemorySize, smem_main);

    proj_kernel<<<384, 128>>>(q, k, v, wq, bq, wv, bv, a);
    gat_main<<<256, 256, smem_main>>>(out_h, out_e, a);
}